// round 4
// baseline (speedup 1.0000x reference)
#include <cuda_runtime.h>
#include <cstdint>

// Problem constants
#define BB 8            // clouds
#define NN 4096         // points per cloud
#define M1 1024         // ceil(0.25*4096) base fps picks per cloud
#define M2 820          // ceil(0.20*4096) extra fps picks per cloud
#define OVSZ 1638       // int(8*1024*0.2) : extra picks kept
#define MTOT 9830       // BB*M1 + OVSZ
#define KNN 16

#define FPS_T 256
#define PPT 16          // 4096 / 256

// Internal int-valued combined indices (kNN consumes these; d_out is float32).
__device__ int g_cidx[MTOT];

// -------------------------------------------------------------------------
// FPS: one block per cloud, 256 threads, 16 points/thread in registers.
// Per step: dist to last pick (explicit no-FMA ops), running min, block
// argmax via packed 64-bit key (dist_bits<<32)|(NN-1-idx): max(key) is
// max dist with smallest-index tie-break (matches jnp.argmax).
// The m2=820 extra-fps sequence is a prefix of the m1=1024 sequence
// (same greedy recursion), so one pass emits base + extra regions.
// -------------------------------------------------------------------------
__global__ void __launch_bounds__(FPS_T, 1)
fps_kernel(const float* __restrict__ pos, float* __restrict__ outf)
{
    __shared__ unsigned long long swarp[FPS_T / 32];
    __shared__ int s_win;

    const int b    = blockIdx.x;
    const int t    = threadIdx.x;
    const int warp = t >> 5, lane = t & 31;
    const unsigned full = 0xffffffffu;

    const float* __restrict__ p = pos + (size_t)b * NN * 3;

    float rx[PPT], ry[PPT], rz[PPT], mind[PPT];
#pragma unroll
    for (int k = 0; k < PPT; ++k) {
        int i = t + k * FPS_T;
        rx[k] = p[3 * i + 0];
        ry[k] = p[3 * i + 1];
        rz[k] = p[3 * i + 2];
        mind[k] = __int_as_float(0x7f800000);  // +inf
    }

    if (t == 0) {
        int g0 = b * NN;
        g_cidx[b * M1] = g0;  outf[b * M1] = (float)g0;      // base pick 0
        if (b == 0) { g_cidx[BB * M1]      = 0;  outf[BB * M1]      = 0.0f; }
        if (b == 1) { g_cidx[BB * M1 + M2] = NN; outf[BB * M1 + M2] = (float)NN; }
    }

    int last = 0;

    for (int s = 1; s < M1; ++s) {
        float lx = __ldg(&p[3 * last + 0]);
        float ly = __ldg(&p[3 * last + 1]);
        float lz = __ldg(&p[3 * last + 2]);

        unsigned long long best = 0ull;
#pragma unroll
        for (int k = 0; k < PPT; ++k) {
            float dx = rx[k] - lx;
            float dy = ry[k] - ly;
            float dz = rz[k] - lz;
            // ((dx*dx + dy*dy) + dz*dz), NO FMA contraction
            float d = __fadd_rn(__fadd_rn(__fmul_rn(dx, dx), __fmul_rn(dy, dy)),
                                __fmul_rn(dz, dz));
            float m = fminf(mind[k], d);
            mind[k] = m;
            // finite >= 0 -> float bits order-preserving as unsigned
            unsigned long long key =
                ((unsigned long long)__float_as_uint(m) << 32) |
                (unsigned)(NN - 1 - (t + k * FPS_T));
            if (key > best) best = key;
        }

#pragma unroll
        for (int off = 16; off > 0; off >>= 1) {
            unsigned long long o = __shfl_xor_sync(full, best, off);
            if (o > best) best = o;
        }
        if (lane == 0) swarp[warp] = best;
        __syncthreads();

        if (warp == 0) {
            unsigned long long v = (lane < FPS_T / 32) ? swarp[lane] : 0ull;
#pragma unroll
            for (int off = 16; off > 0; off >>= 1) {
                unsigned long long o = __shfl_xor_sync(full, v, off);
                if (o > v) v = o;
            }
            if (lane == 0) {
                int win = NN - 1 - (int)(unsigned)(v & 0xffffffffull);
                s_win = win;
                int g = b * NN + win;
                g_cidx[b * M1 + s] = g;  outf[b * M1 + s] = (float)g;
                if (b == 0 && s < M2) {
                    g_cidx[BB * M1 + s] = g;  outf[BB * M1 + s] = (float)g;
                }
                if (b == 1 && s < (OVSZ - M2)) {
                    g_cidx[BB * M1 + M2 + s] = g;  outf[BB * M1 + M2 + s] = (float)g;
                }
            }
        }
        __syncthreads();
        last = s_win;
    }
}

// -------------------------------------------------------------------------
// kNN: grid (chunks, 8 clouds), 128 queries per block. Cloud cached in
// smem as two 2048-point tiles (24 KB), ascending index order. Per-thread
// sorted top-16 in registers; strict-< insertion keeps jax top_k stable
// tie order (earlier index first on equal distance).
// -------------------------------------------------------------------------
#define TILE 2048

__global__ void __launch_bounds__(128)
knn_kernel(const float* __restrict__ pos,
           float* __restrict__ rowf, float* __restrict__ colf)
{
    __shared__ float sx[TILE];
    __shared__ float sy[TILE];
    __shared__ float sz[TILE];

    const int b   = blockIdx.y;
    const int cnt = M1 + (b == 0 ? M2 : (b == 1 ? (OVSZ - M2) : 0));
    if (blockIdx.x * 128 >= cnt) return;          // block-uniform

    const int  q      = blockIdx.x * 128 + threadIdx.x;
    const bool active = (q < cnt);

    int posc = 0, qi = 0;
    float qx = 0.f, qy = 0.f, qz = 0.f;
    if (active) {
        if (q < M1) posc = b * M1 + q;
        else        posc = (b == 0 ? BB * M1 : BB * M1 + M2) + (q - M1);
        int gq = g_cidx[posc];
        qi = gq & (NN - 1);
        const float* qp = pos + ((size_t)b * NN + qi) * 3;
        qx = qp[0]; qy = qp[1]; qz = qp[2];
    }

    float nd[KNN];
    int   ni[KNN];
#pragma unroll
    for (int k = 0; k < KNN; ++k) { nd[k] = __int_as_float(0x7f800000); ni[k] = 0; }

    for (int tile = 0; tile < NN / TILE; ++tile) {
        __syncthreads();
        const float* __restrict__ p = pos + ((size_t)b * NN + tile * TILE) * 3;
        for (int j = threadIdx.x; j < TILE * 3; j += 128) {
            float v = p[j];
            int pt = j / 3, c = j - 3 * pt;
            if (c == 0) sx[pt] = v; else if (c == 1) sy[pt] = v; else sz[pt] = v;
        }
        __syncthreads();

        if (active) {
            const int base = tile * TILE;
            for (int j = 0; j < TILE; ++j) {
                float dx = sx[j] - qx;
                float dy = sy[j] - qy;
                float dz = sz[j] - qz;
                float d = __fadd_rn(__fadd_rn(__fmul_rn(dx, dx), __fmul_rn(dy, dy)),
                                    __fmul_rn(dz, dz));
                if (d < nd[KNN - 1]) {
                    nd[KNN - 1] = d; ni[KNN - 1] = base + j;
#pragma unroll
                    for (int k = KNN - 1; k > 0; --k) {
                        if (nd[k] < nd[k - 1]) {  // strict: equal keeps earlier idx first
                            float td = nd[k]; nd[k] = nd[k - 1]; nd[k - 1] = td;
                            int   ti = ni[k]; ni[k] = ni[k - 1]; ni[k - 1] = ti;
                        }
                    }
                }
            }
        }
    }

    if (active && rowf != nullptr) {
#pragma unroll
        for (int k = 0; k < KNN; ++k) {
            rowf[posc * KNN + k] = (float)posc;
            colf[posc * KNN + k] = (float)(b * NN + ni[k]);
        }
    }
}

// -------------------------------------------------------------------------
extern "C" void kernel_launch(void* const* d_in, const int* in_sizes, int n_in,
                              void* d_out, int out_size)
{
    // pos = the largest input (robust to ordering and element/byte units:
    // pos is 98304 elems / 393216 bytes, batch is 32768 / 131072).
    const float* pos = (const float*)d_in[0];
    int best = -1;
    for (int i = 0; i < n_in; ++i) {
        if (in_sizes[i] > best) { best = in_sizes[i]; pos = (const float*)d_in[i]; }
    }

    float* outf = (float*)d_out;

    // Output layout: [combined_idx (MTOT)] [row (MTOT*K)] [col (MTOT*K)],
    // all as float32 values. Skip row/col if the buffer lacks room.
    float* rowf = nullptr;
    float* colf = nullptr;
    if (out_size >= MTOT + 2 * MTOT * KNN) {
        rowf = outf + MTOT;
        colf = outf + MTOT + (size_t)MTOT * KNN;
    }

    fps_kernel<<<BB, FPS_T>>>(pos, outf);

    dim3 grid((M1 + M2 + 127) / 128, BB);
    knn_kernel<<<grid, 128>>>(pos, rowf, colf);
}

// round 5
// speedup vs baseline: 1.2628x; 1.2628x over previous
#include <cuda_runtime.h>
#include <cstdint>

// Problem constants
#define BB 8            // clouds
#define NN 4096         // points per cloud
#define M1 1024         // ceil(0.25*4096) base fps picks per cloud
#define M2 820          // ceil(0.20*4096) extra fps picks per cloud
#define OVSZ 1638       // int(8*1024*0.2) : extra picks kept
#define MTOT 9830       // BB*M1 + OVSZ
#define KNN 16

#define FPS_T 256
#define PAIRS 8         // 16 points per thread, as 8 f32x2 pairs

typedef unsigned long long u64;

// Internal int-valued combined indices (kNN consumes these; d_out is float32).
__device__ int g_cidx[MTOT];

// Packed f32x2 helpers (sm_100+: two rn.f32 ops in one instruction, bit-identical)
#define ADD2(out, a, b) asm("add.rn.f32x2 %0, %1, %2;" : "=l"(out) : "l"(a), "l"(b))
#define MUL2(out, a, b) asm("mul.rn.f32x2 %0, %1, %2;" : "=l"(out) : "l"(a), "l"(b))
#define PACK2(out, lo, hi) asm("mov.b64 %0, {%1, %2};" : "=l"(out) : "r"(lo), "r"(hi))
#define UNPK2(lo, hi, in)  asm("mov.b64 {%0, %1}, %2;" : "=r"(lo), "=r"(hi) : "l"(in))

// -------------------------------------------------------------------------
// FPS: one block per cloud, 256 threads, 16 points/thread in registers
// (packed as f32x2 pairs). Per step:
//   - packed diff/sq/sum (add/mul.rn.f32x2 == two scalar .rn ops, exact)
//   - running min + per-thread argmax (ascending idx -> smallest-idx ties)
//   - warp argmax via REDUX: max on dist bits, then min on candidate idx
//   - ONE barrier: each warp posts (dist<<32)|(NN-1-idx) to a parity
//     double-buffered smem slot; every thread computes the block winner
//     redundantly from 8 broadcast LDS reads (no 2nd barrier/broadcast).
// m2 extra-fps picks are a prefix of the m1 sequence -> one pass emits all.
// -------------------------------------------------------------------------
__global__ void __launch_bounds__(FPS_T, 1)
fps_kernel(const float* __restrict__ pos, float* __restrict__ outf)
{
    __shared__ u64 swk[2][FPS_T / 32];

    const int b    = blockIdx.x;
    const int t    = threadIdx.x;
    const int warp = t >> 5, lane = t & 31;
    const unsigned full = 0xffffffffu;

    const float* __restrict__ p = pos + (size_t)b * NN * 3;

    u64 rx2[PAIRS], ry2[PAIRS], rz2[PAIRS];
    float mind[2 * PAIRS];
#pragma unroll
    for (int m = 0; m < PAIRS; ++m) {
        int i0 = t + (2 * m)     * FPS_T;
        int i1 = t + (2 * m + 1) * FPS_T;
        float x0 = p[3 * i0 + 0], x1 = p[3 * i1 + 0];
        float y0 = p[3 * i0 + 1], y1 = p[3 * i1 + 1];
        float z0 = p[3 * i0 + 2], z1 = p[3 * i1 + 2];
        PACK2(rx2[m], __float_as_uint(x0), __float_as_uint(x1));
        PACK2(ry2[m], __float_as_uint(y0), __float_as_uint(y1));
        PACK2(rz2[m], __float_as_uint(z0), __float_as_uint(z1));
        mind[2 * m]     = __int_as_float(0x7f800000);
        mind[2 * m + 1] = __int_as_float(0x7f800000);
    }

    if (t == 0) {
        int g0 = b * NN;
        g_cidx[b * M1] = g0;  outf[b * M1] = (float)g0;
        if (b == 0) { g_cidx[BB * M1]      = 0;  outf[BB * M1]      = 0.0f; }
        if (b == 1) { g_cidx[BB * M1 + M2] = NN; outf[BB * M1 + M2] = (float)NN; }
    }

    int last = 0;

    for (int s = 1; s < M1; ++s) {
        float lx = __ldg(&p[3 * last + 0]);
        float ly = __ldg(&p[3 * last + 1]);
        float lz = __ldg(&p[3 * last + 2]);
        // negate once: (r - l) == (r + (-l)), exact
        unsigned nlx = __float_as_uint(-lx);
        unsigned nly = __float_as_uint(-ly);
        unsigned nlz = __float_as_uint(-lz);
        u64 nlx2, nly2, nlz2;
        PACK2(nlx2, nlx, nlx);
        PACK2(nly2, nly, nly);
        PACK2(nlz2, nlz, nlz);

        float bestv = -1.0f;
        int   besti = 0;
#pragma unroll
        for (int m = 0; m < PAIRS; ++m) {
            u64 dx2, dy2, dz2, xx2, yy2, zz2, t2, s2;
            ADD2(dx2, rx2[m], nlx2);
            ADD2(dy2, ry2[m], nly2);
            ADD2(dz2, rz2[m], nlz2);
            MUL2(xx2, dx2, dx2);
            MUL2(yy2, dy2, dy2);
            MUL2(zz2, dz2, dz2);
            ADD2(t2, xx2, yy2);
            ADD2(s2, t2, zz2);
            unsigned b0, b1;
            UNPK2(b0, b1, s2);
            float m0 = fminf(mind[2 * m],     __uint_as_float(b0));
            float m1 = fminf(mind[2 * m + 1], __uint_as_float(b1));
            mind[2 * m]     = m0;
            mind[2 * m + 1] = m1;
            // ascending idx scan + strict > keeps smallest idx on tie
            if (m0 > bestv) { bestv = m0; besti = t + (2 * m)     * FPS_T; }
            if (m1 > bestv) { bestv = m1; besti = t + (2 * m + 1) * FPS_T; }
        }

        // Warp argmax: dist bits are order-preserving (>= 0)
        unsigned bv   = __float_as_uint(bestv);
        unsigned wmax = __reduce_max_sync(full, bv);
        unsigned cand = (bv == wmax) ? (unsigned)besti : 0xffffffffu;
        unsigned widx = __reduce_min_sync(full, cand);

        if (lane == 0)
            swk[s & 1][warp] = ((u64)wmax << 32) | (unsigned)(NN - 1 - (int)widx);
        __syncthreads();

        u64 blk = swk[s & 1][0];
#pragma unroll
        for (int w = 1; w < FPS_T / 32; ++w) {
            u64 v = swk[s & 1][w];
            if (v > blk) blk = v;
        }
        int win = NN - 1 - (int)(unsigned)(blk & 0xffffffffu);

        if (t == 0) {
            int g = b * NN + win;
            g_cidx[b * M1 + s] = g;  outf[b * M1 + s] = (float)g;
            if (b == 0 && s < M2) {
                g_cidx[BB * M1 + s] = g;  outf[BB * M1 + s] = (float)g;
            }
            if (b == 1 && s < (OVSZ - M2)) {
                g_cidx[BB * M1 + M2 + s] = g;  outf[BB * M1 + M2 + s] = (float)g;
            }
        }
        last = win;
    }
}

// -------------------------------------------------------------------------
// kNN: 4-way split per query. Block = 128 threads = 32 queries x 4 parts
// (part == warp id; all 32 lanes of a warp share the same point index j
// -> broadcast LDS). Each thread scans a stride-4 subset of the cloud and
// keeps a sorted top-16 of packed keys (dist_bits<<32)|local_idx -- key
// order == (d asc, idx asc) == jax top_k stable order, so scan order and
// partitioning are semantics-free. 4 sorted lists merge via smem.
// -------------------------------------------------------------------------
#define QB 32           // queries per block
#define PARTS 4
#define KTILE 2048

__global__ void __launch_bounds__(128)
knn_kernel(const float* __restrict__ pos,
           float* __restrict__ rowf, float* __restrict__ colf)
{
    __shared__ float sx[KTILE];
    __shared__ float sy[KTILE];
    __shared__ float sz[KTILE];
    __shared__ u64   smk[QB][PARTS][KNN];    // 16 KB

    const int b   = blockIdx.y;
    const int cnt = M1 + (b == 0 ? M2 : (b == 1 ? (OVSZ - M2) : 0));
    if (blockIdx.x * QB >= cnt) return;       // block-uniform

    const int tid  = threadIdx.x;
    const int q    = tid & (QB - 1);
    const int part = tid >> 5;                // == warp id

    const int  q0     = blockIdx.x * QB + q;
    const bool active = (q0 < cnt);

    int posc = 0;
    float qx = 0.f, qy = 0.f, qz = 0.f;
    if (active) {
        if (q0 < M1) posc = b * M1 + q0;
        else         posc = (b == 0 ? BB * M1 : BB * M1 + M2) + (q0 - M1);
        int qi = g_cidx[posc] & (NN - 1);
        const float* qp = pos + ((size_t)b * NN + qi) * 3;
        qx = qp[0]; qy = qp[1]; qz = qp[2];
    }

    u64 keys[KNN];
#pragma unroll
    for (int k = 0; k < KNN; ++k) keys[k] = ~0ull;

    for (int tile = 0; tile < NN / KTILE; ++tile) {
        __syncthreads();
        const float* __restrict__ p = pos + ((size_t)b * NN + tile * KTILE) * 3;
        for (int j = tid; j < KTILE * 3; j += 128) {
            float v = p[j];
            int pt = j / 3, c = j - 3 * pt;
            if (c == 0) sx[pt] = v; else if (c == 1) sy[pt] = v; else sz[pt] = v;
        }
        __syncthreads();

        if (active) {
            const int base = tile * KTILE;
            for (int j = part; j < KTILE; j += PARTS) {
                float dx = sx[j] - qx;
                float dy = sy[j] - qy;
                float dz = sz[j] - qz;
                float d = __fadd_rn(__fadd_rn(__fmul_rn(dx, dx), __fmul_rn(dy, dy)),
                                    __fmul_rn(dz, dz));
                u64 key = ((u64)__float_as_uint(d) << 32) | (unsigned)(base + j);
                if (key < keys[KNN - 1]) {
                    keys[KNN - 1] = key;
#pragma unroll
                    for (int k = KNN - 1; k > 0; --k) {
                        if (keys[k] < keys[k - 1]) {
                            u64 tk = keys[k]; keys[k] = keys[k - 1]; keys[k - 1] = tk;
                        }
                    }
                }
            }
        }
    }

    // Publish per-part sorted lists
#pragma unroll
    for (int k = 0; k < KNN; ++k) smk[q][part][k] = keys[k];
    __syncthreads();

    // One thread per query merges the 4 sorted 16-lists (take 16 smallest)
    if (tid < QB && active && rowf != nullptr) {
        int i0 = 0, i1 = 0, i2 = 0, i3 = 0;
        float fposc = (float)posc;
#pragma unroll
        for (int k = 0; k < KNN; ++k) {
            u64 h0 = smk[q][0][i0];
            u64 h1 = smk[q][1][i1];
            u64 h2 = smk[q][2][i2];
            u64 h3 = smk[q][3][i3];
            u64 m01 = (h0 <= h1) ? h0 : h1;
            u64 m23 = (h2 <= h3) ? h2 : h3;
            u64 mk  = (m01 <= m23) ? m01 : m23;
            if (mk == h0)      ++i0;
            else if (mk == h1) ++i1;
            else if (mk == h2) ++i2;
            else               ++i3;
            int li = (int)(unsigned)(mk & 0xffffffffu);
            rowf[posc * KNN + k] = fposc;
            colf[posc * KNN + k] = (float)(b * NN + li);
        }
    }
}

// -------------------------------------------------------------------------
extern "C" void kernel_launch(void* const* d_in, const int* in_sizes, int n_in,
                              void* d_out, int out_size)
{
    // pos = the largest input (98304 elems; batch is 32768)
    const float* pos = (const float*)d_in[0];
    int best = -1;
    for (int i = 0; i < n_in; ++i) {
        if (in_sizes[i] > best) { best = in_sizes[i]; pos = (const float*)d_in[i]; }
    }

    float* outf = (float*)d_out;
    float* rowf = nullptr;
    float* colf = nullptr;
    if (out_size >= MTOT + 2 * MTOT * KNN) {
        rowf = outf + MTOT;
        colf = outf + MTOT + (size_t)MTOT * KNN;
    }

    fps_kernel<<<BB, FPS_T>>>(pos, outf);

    dim3 grid((M1 + M2 + QB - 1) / QB, BB);   // 58 x 8 covers worst cloud (1844)
    knn_kernel<<<grid, 128>>>(pos, rowf, colf);
}

// round 6
// speedup vs baseline: 2.2144x; 1.7536x over previous
#include <cuda_runtime.h>
#include <cstdint>

// Problem constants
#define BB 8            // clouds
#define NN 4096         // points per cloud
#define M1 1024         // ceil(0.25*4096) base fps picks per cloud
#define M2 820          // ceil(0.20*4096) extra fps picks per cloud
#define OVSZ 1638       // int(8*1024*0.2) : extra picks kept
#define MTOT 9830       // BB*M1 + OVSZ
#define KNN 16

#define FPS_T 256
#define PAIRS 8         // 16 points per thread, as 8 f32x2 pairs

typedef unsigned long long u64;

// Internal int-valued combined indices (kNN consumes these; d_out is float32).
__device__ int g_cidx[MTOT];

// Packed f32x2 helpers (two rn.f32 ops in one instruction, bit-identical)
#define ADD2(out, a, b) asm("add.rn.f32x2 %0, %1, %2;" : "=l"(out) : "l"(a), "l"(b))
#define MUL2(out, a, b) asm("mul.rn.f32x2 %0, %1, %2;" : "=l"(out) : "l"(a), "l"(b))
#define PACK2(out, lo, hi) asm("mov.b64 %0, {%1, %2};" : "=l"(out) : "r"(lo), "r"(hi))
#define UNPK2(lo, hi, in)  asm("mov.b64 {%0, %1}, %2;" : "=r"(lo), "=r"(hi) : "l"(in))

// -------------------------------------------------------------------------
// FPS (unchanged from round 5): one block per cloud, 256 threads,
// 16 points/thread in registers as f32x2 pairs; REDUX warp argmax;
// single barrier per step with parity-double-buffered warp slots.
// -------------------------------------------------------------------------
__global__ void __launch_bounds__(FPS_T, 1)
fps_kernel(const float* __restrict__ pos, float* __restrict__ outf)
{
    __shared__ u64 swk[2][FPS_T / 32];

    const int b    = blockIdx.x;
    const int t    = threadIdx.x;
    const int warp = t >> 5, lane = t & 31;
    const unsigned full = 0xffffffffu;

    const float* __restrict__ p = pos + (size_t)b * NN * 3;

    u64 rx2[PAIRS], ry2[PAIRS], rz2[PAIRS];
    float mind[2 * PAIRS];
#pragma unroll
    for (int m = 0; m < PAIRS; ++m) {
        int i0 = t + (2 * m)     * FPS_T;
        int i1 = t + (2 * m + 1) * FPS_T;
        float x0 = p[3 * i0 + 0], x1 = p[3 * i1 + 0];
        float y0 = p[3 * i0 + 1], y1 = p[3 * i1 + 1];
        float z0 = p[3 * i0 + 2], z1 = p[3 * i1 + 2];
        PACK2(rx2[m], __float_as_uint(x0), __float_as_uint(x1));
        PACK2(ry2[m], __float_as_uint(y0), __float_as_uint(y1));
        PACK2(rz2[m], __float_as_uint(z0), __float_as_uint(z1));
        mind[2 * m]     = __int_as_float(0x7f800000);
        mind[2 * m + 1] = __int_as_float(0x7f800000);
    }

    if (t == 0) {
        int g0 = b * NN;
        g_cidx[b * M1] = g0;  outf[b * M1] = (float)g0;
        if (b == 0) { g_cidx[BB * M1]      = 0;  outf[BB * M1]      = 0.0f; }
        if (b == 1) { g_cidx[BB * M1 + M2] = NN; outf[BB * M1 + M2] = (float)NN; }
    }

    int last = 0;

    for (int s = 1; s < M1; ++s) {
        float lx = __ldg(&p[3 * last + 0]);
        float ly = __ldg(&p[3 * last + 1]);
        float lz = __ldg(&p[3 * last + 2]);
        unsigned nlx = __float_as_uint(-lx);
        unsigned nly = __float_as_uint(-ly);
        unsigned nlz = __float_as_uint(-lz);
        u64 nlx2, nly2, nlz2;
        PACK2(nlx2, nlx, nlx);
        PACK2(nly2, nly, nly);
        PACK2(nlz2, nlz, nlz);

        float bestv = -1.0f;
        int   besti = 0;
#pragma unroll
        for (int m = 0; m < PAIRS; ++m) {
            u64 dx2, dy2, dz2, xx2, yy2, zz2, t2, s2;
            ADD2(dx2, rx2[m], nlx2);
            ADD2(dy2, ry2[m], nly2);
            ADD2(dz2, rz2[m], nlz2);
            MUL2(xx2, dx2, dx2);
            MUL2(yy2, dy2, dy2);
            MUL2(zz2, dz2, dz2);
            ADD2(t2, xx2, yy2);
            ADD2(s2, t2, zz2);
            unsigned b0, b1;
            UNPK2(b0, b1, s2);
            float m0 = fminf(mind[2 * m],     __uint_as_float(b0));
            float m1 = fminf(mind[2 * m + 1], __uint_as_float(b1));
            mind[2 * m]     = m0;
            mind[2 * m + 1] = m1;
            if (m0 > bestv) { bestv = m0; besti = t + (2 * m)     * FPS_T; }
            if (m1 > bestv) { bestv = m1; besti = t + (2 * m + 1) * FPS_T; }
        }

        unsigned bv   = __float_as_uint(bestv);
        unsigned wmax = __reduce_max_sync(full, bv);
        unsigned cand = (bv == wmax) ? (unsigned)besti : 0xffffffffu;
        unsigned widx = __reduce_min_sync(full, cand);

        if (lane == 0)
            swk[s & 1][warp] = ((u64)wmax << 32) | (unsigned)(NN - 1 - (int)widx);
        __syncthreads();

        u64 blk = swk[s & 1][0];
#pragma unroll
        for (int w = 1; w < FPS_T / 32; ++w) {
            u64 v = swk[s & 1][w];
            if (v > blk) blk = v;
        }
        int win = NN - 1 - (int)(unsigned)(blk & 0xffffffffu);

        if (t == 0) {
            int g = b * NN + win;
            g_cidx[b * M1 + s] = g;  outf[b * M1 + s] = (float)g;
            if (b == 0 && s < M2) {
                g_cidx[BB * M1 + s] = g;  outf[BB * M1 + s] = (float)g;
            }
            if (b == 1 && s < (OVSZ - M2)) {
                g_cidx[BB * M1 + M2 + s] = g;  outf[BB * M1 + M2 + s] = (float)g;
            }
        }
        last = win;
    }
}

// -------------------------------------------------------------------------
// kNN: ONE QUERY PER WARP, lane-distributed sorted top-16.
//   - Lanes 0..15 hold the sorted (ascending) u64 keys (dist<<32)|idx;
//     key order == (d asc, idx asc) == jax top_k stable order.
//   - Per trip: lane l evaluates point j = trip*32 + l (coalesced GMEM,
//     cloud stays L1-resident), ballots key < list[15]; qualifiers are
//     inserted serially in ascending-lane (== ascending-idx) order via an
//     O(1) warp shift: pos = popc(ballot(mykey < cand)), shfl_up by 1.
//     Each candidate is re-checked vs the updated threshold, so this is
//     bit-exact sequential insertion.
//   - Output: lane k IS neighbor k (no merge).
// -------------------------------------------------------------------------
#define KNN_T 256            // 8 warps = 8 queries per block
#define WPB (KNN_T / 32)

__global__ void __launch_bounds__(KNN_T)
knn_kernel(const float* __restrict__ pos,
           float* __restrict__ rowf, float* __restrict__ colf)
{
    const int lane = threadIdx.x & 31;
    const int wid  = threadIdx.x >> 5;
    const unsigned full = 0xffffffffu;

    const int posc = blockIdx.x * WPB + wid;      // query = position in combined_idx
    if (posc >= MTOT) return;                     // warp-uniform

    // cloud id for this combined position
    int b;
    if (posc < BB * M1) b = posc >> 10;           // base region
    else { int e = posc - BB * M1; b = (e < M2) ? 0 : 1; }

    const float* __restrict__ p = pos + (size_t)b * NN * 3;

    const int qi = g_cidx[posc] & (NN - 1);       // local query index (broadcast load)
    const float qx = __ldg(&p[3 * qi + 0]);
    const float qy = __ldg(&p[3 * qi + 1]);
    const float qz = __ldg(&p[3 * qi + 2]);

    u64 mykey = ~0ull;                            // lanes 0..15: sorted list; others dummy
    u64 thr   = ~0ull;                            // current list[15]

    for (int trip = 0; trip < NN / 32; ++trip) {
        const int j = trip * 32 + lane;
        float dx = __ldg(&p[3 * j + 0]) - qx;
        float dy = __ldg(&p[3 * j + 1]) - qy;
        float dz = __ldg(&p[3 * j + 2]) - qz;
        float d = __fadd_rn(__fadd_rn(__fmul_rn(dx, dx), __fmul_rn(dy, dy)),
                            __fmul_rn(dz, dz));
        u64 ckey = ((u64)__float_as_uint(d) << 32) | (unsigned)j;

        unsigned qmask = __ballot_sync(full, ckey < thr);
        while (qmask) {
            int leader = __ffs(qmask) - 1;        // lowest lane = smallest idx
            qmask &= qmask - 1;
            u64 cand = __shfl_sync(full, ckey, leader);
            if (cand < thr) {                     // re-check vs updated threshold
                unsigned below = __ballot_sync(full, mykey < cand) & 0xffffu;
                int pos16 = __popc(below);        // insertion position
                u64 up = __shfl_up_sync(full, mykey, 1);
                if (lane >= pos16) mykey = (lane == pos16) ? cand : up;
                thr = __shfl_sync(full, mykey, 15);
            }
        }
    }

    // Emit: lane k is the k-th nearest neighbor.
    if (lane < KNN && rowf != nullptr) {
        rowf[posc * KNN + lane] = (float)posc;
        colf[posc * KNN + lane] = (float)(b * NN + (int)(unsigned)(mykey & 0xffffffffu));
    }
}

// -------------------------------------------------------------------------
extern "C" void kernel_launch(void* const* d_in, const int* in_sizes, int n_in,
                              void* d_out, int out_size)
{
    // pos = the largest input (98304 elems; batch is 32768)
    const float* pos = (const float*)d_in[0];
    int best = -1;
    for (int i = 0; i < n_in; ++i) {
        if (in_sizes[i] > best) { best = in_sizes[i]; pos = (const float*)d_in[i]; }
    }

    float* outf = (float*)d_out;
    float* rowf = nullptr;
    float* colf = nullptr;
    if (out_size >= MTOT + 2 * MTOT * KNN) {
        rowf = outf + MTOT;
        colf = outf + MTOT + (size_t)MTOT * KNN;
    }

    fps_kernel<<<BB, FPS_T>>>(pos, outf);

    knn_kernel<<<(MTOT + WPB - 1) / WPB, KNN_T>>>(pos, rowf, colf);
}

// round 7
// speedup vs baseline: 2.2360x; 1.0097x over previous
#include <cuda_runtime.h>
#include <cstdint>

// Problem constants
#define BB 8            // clouds
#define NN 4096         // points per cloud
#define M1 1024         // ceil(0.25*4096) base fps picks per cloud
#define M2 820          // ceil(0.20*4096) extra fps picks per cloud
#define OVSZ 1638       // int(8*1024*0.2) : extra picks kept
#define MTOT 9830       // BB*M1 + OVSZ
#define KNN 16

#define FPS_T 256
#define PPT 16          // points per thread (contiguous)
#define PAIRS 8

typedef unsigned long long u64;

// Internal int-valued combined indices (kNN consumes these; d_out is float32).
__device__ int g_cidx[MTOT];

// Packed f32x2 helpers (two rn.f32 ops in one instruction, bit-identical)
#define ADD2(out, a, b) asm("add.rn.f32x2 %0, %1, %2;" : "=l"(out) : "l"(a), "l"(b))
#define MUL2(out, a, b) asm("mul.rn.f32x2 %0, %1, %2;" : "=l"(out) : "l"(a), "l"(b))
#define PACK2(out, lo, hi) asm("mov.b64 %0, {%1, %2};" : "=l"(out) : "r"(lo), "r"(hi))
#define UNPK2(lo, hi, in)  asm("mov.b64 {%0, %1}, %2;" : "=r"(lo), "=r"(hi) : "l"(in))

// -------------------------------------------------------------------------
// FPS: one block per cloud, 256 threads, CONTIGUOUS 16 points/thread
// (so index order == lane order == warp order). Per step:
//   - packed f32x2 distance + running min (exact, non-FMA)
//   - per-thread argmax with ascending scan (strict > => smallest idx tie)
//   - warp stage: ONE __reduce_max_sync on dist bits; the first tied lane
//     (ballot prefix test) is the min-index owner and posts the packed
//     slot (dist<<32)|(NN-1-idx) itself -- no REDUX.min, no shfl.
//   - ONE barrier; all threads scan the 8 parity-buffered slots.
// m2 extra-fps picks are a prefix of the m1 sequence -> one pass emits all.
// -------------------------------------------------------------------------
__global__ void __launch_bounds__(FPS_T, 1)
fps_kernel(const float* __restrict__ pos, float* __restrict__ outf)
{
    __shared__ alignas(16) u64 swk[2][FPS_T / 32];

    const int b    = blockIdx.x;
    const int t    = threadIdx.x;
    const int warp = t >> 5, lane = t & 31;
    const unsigned full = 0xffffffffu;

    const float* __restrict__ p = pos + (size_t)b * NN * 3;
    const int base = t * PPT;                   // contiguous ownership

    u64 rx2[PAIRS], ry2[PAIRS], rz2[PAIRS];
    float mind[PPT];
#pragma unroll
    for (int m = 0; m < PAIRS; ++m) {
        int i0 = base + 2 * m;
        float x0 = p[3 * i0 + 0], y0 = p[3 * i0 + 1], z0 = p[3 * i0 + 2];
        float x1 = p[3 * i0 + 3], y1 = p[3 * i0 + 4], z1 = p[3 * i0 + 5];
        PACK2(rx2[m], __float_as_uint(x0), __float_as_uint(x1));
        PACK2(ry2[m], __float_as_uint(y0), __float_as_uint(y1));
        PACK2(rz2[m], __float_as_uint(z0), __float_as_uint(z1));
        mind[2 * m]     = __int_as_float(0x7f800000);
        mind[2 * m + 1] = __int_as_float(0x7f800000);
    }

    if (t == 0) {
        int g0 = b * NN;
        g_cidx[b * M1] = g0;  outf[b * M1] = (float)g0;
        if (b == 0) { g_cidx[BB * M1]      = 0;  outf[BB * M1]      = 0.0f; }
        if (b == 1) { g_cidx[BB * M1 + M2] = NN; outf[BB * M1 + M2] = (float)NN; }
    }

    int last = 0;

    for (int s = 1; s < M1; ++s) {
        float lx = __ldg(&p[3 * last + 0]);
        float ly = __ldg(&p[3 * last + 1]);
        float lz = __ldg(&p[3 * last + 2]);
        unsigned nlx = __float_as_uint(-lx);
        unsigned nly = __float_as_uint(-ly);
        unsigned nlz = __float_as_uint(-lz);
        u64 nlx2, nly2, nlz2;
        PACK2(nlx2, nlx, nlx);
        PACK2(nly2, nly, nly);
        PACK2(nlz2, nlz, nlz);

        float bestv = -1.0f;
        int   besti = base;
#pragma unroll
        for (int m = 0; m < PAIRS; ++m) {
            u64 dx2, dy2, dz2, xx2, yy2, zz2, t2, s2;
            ADD2(dx2, rx2[m], nlx2);
            ADD2(dy2, ry2[m], nly2);
            ADD2(dz2, rz2[m], nlz2);
            MUL2(xx2, dx2, dx2);
            MUL2(yy2, dy2, dy2);
            MUL2(zz2, dz2, dz2);
            ADD2(t2, xx2, yy2);
            ADD2(s2, t2, zz2);
            unsigned b0, b1;
            UNPK2(b0, b1, s2);
            float m0 = fminf(mind[2 * m],     __uint_as_float(b0));
            float m1 = fminf(mind[2 * m + 1], __uint_as_float(b1));
            mind[2 * m]     = m0;
            mind[2 * m + 1] = m1;
            // ascending idx + strict > keeps smallest idx on tie
            if (m0 > bestv) { bestv = m0; besti = base + 2 * m;     }
            if (m1 > bestv) { bestv = m1; besti = base + 2 * m + 1; }
        }

        // Warp stage: one REDUX; first tied lane == min-index owner
        // (contiguous ownership: lower lane => strictly lower indices).
        unsigned bv   = __float_as_uint(bestv);
        unsigned wmax = __reduce_max_sync(full, bv);
        unsigned tied = __ballot_sync(full, bv == wmax);
        if ((bv == wmax) && ((tied & ((1u << lane) - 1u)) == 0u)) {
            swk[s & 1][warp] = ((u64)wmax << 32) | (unsigned)(NN - 1 - besti);
        }
        __syncthreads();

        // Block stage: all threads redundantly scan 8 slots (warp order ==
        // index order; packed key handles ties exactly anyway).
        u64 blk = swk[s & 1][0];
#pragma unroll
        for (int w = 1; w < FPS_T / 32; ++w) {
            u64 v = swk[s & 1][w];
            if (v > blk) blk = v;
        }
        int win = NN - 1 - (int)(unsigned)(blk & 0xffffffffu);

        if (t == 0) {
            int g = b * NN + win;
            g_cidx[b * M1 + s] = g;  outf[b * M1 + s] = (float)g;
            if (b == 0 && s < M2) {
                g_cidx[BB * M1 + s] = g;  outf[BB * M1 + s] = (float)g;
            }
            if (b == 1 && s < (OVSZ - M2)) {
                g_cidx[BB * M1 + M2 + s] = g;  outf[BB * M1 + M2 + s] = (float)g;
            }
        }
        last = win;
    }
}

// -------------------------------------------------------------------------
// kNN: one query per warp, lane-distributed sorted top-16 (round-6 design).
// Runs ONLY the 8192 base-region queries; extra-region queries are exact
// duplicates and get copied afterwards.
// -------------------------------------------------------------------------
#define KNN_T 256            // 8 warps = 8 queries per block
#define WPB (KNN_T / 32)

__global__ void __launch_bounds__(KNN_T)
knn_kernel(const float* __restrict__ pos,
           float* __restrict__ rowf, float* __restrict__ colf)
{
    const int lane = threadIdx.x & 31;
    const int wid  = threadIdx.x >> 5;
    const unsigned full = 0xffffffffu;

    const int posc = blockIdx.x * WPB + wid;      // base-region position
    const int b    = posc >> 10;                  // cloud id

    const float* __restrict__ p = pos + (size_t)b * NN * 3;

    const int qi = g_cidx[posc] & (NN - 1);
    const float qx = __ldg(&p[3 * qi + 0]);
    const float qy = __ldg(&p[3 * qi + 1]);
    const float qz = __ldg(&p[3 * qi + 2]);

    u64 mykey = ~0ull;                            // lanes 0..15: sorted list
    u64 thr   = ~0ull;                            // current list[15]

    for (int trip = 0; trip < NN / 32; ++trip) {
        const int j = trip * 32 + lane;
        float dx = __ldg(&p[3 * j + 0]) - qx;
        float dy = __ldg(&p[3 * j + 1]) - qy;
        float dz = __ldg(&p[3 * j + 2]) - qz;
        float d = __fadd_rn(__fadd_rn(__fmul_rn(dx, dx), __fmul_rn(dy, dy)),
                            __fmul_rn(dz, dz));
        u64 ckey = ((u64)__float_as_uint(d) << 32) | (unsigned)j;

        unsigned qmask = __ballot_sync(full, ckey < thr);
        while (qmask) {
            int leader = __ffs(qmask) - 1;        // lowest lane = smallest idx
            qmask &= qmask - 1;
            u64 cand = __shfl_sync(full, ckey, leader);
            if (cand < thr) {                     // re-check vs updated threshold
                unsigned below = __ballot_sync(full, mykey < cand) & 0xffffu;
                int pos16 = __popc(below);
                u64 up = __shfl_up_sync(full, mykey, 1);
                if (lane >= pos16) mykey = (lane == pos16) ? cand : up;
                thr = __shfl_sync(full, mykey, 15);
            }
        }
    }

    if (lane < KNN && rowf != nullptr) {
        rowf[posc * KNN + lane] = (float)posc;
        colf[posc * KNN + lane] = (float)(b * NN + (int)(unsigned)(mykey & 0xffffffffu));
    }
}

// -------------------------------------------------------------------------
// Extra-region duplication: query at extra slot j is the same (point,cloud)
// as base slot src(j), so its col row is identical; row = its own posc.
// -------------------------------------------------------------------------
__global__ void dup_kernel(float* __restrict__ rowf, float* __restrict__ colf)
{
    int i = blockIdx.x * blockDim.x + threadIdx.x;
    if (i >= OVSZ * KNN) return;
    int j = i / KNN, k = i - j * KNN;
    int dst = BB * M1 + j;
    int src = (j < M2) ? j : (M1 + (j - M2));   // cloud0 base | cloud1 base
    rowf[dst * KNN + k] = (float)dst;
    colf[dst * KNN + k] = colf[src * KNN + k];
}

// -------------------------------------------------------------------------
extern "C" void kernel_launch(void* const* d_in, const int* in_sizes, int n_in,
                              void* d_out, int out_size)
{
    // pos = the largest input (98304 elems; batch is 32768)
    const float* pos = (const float*)d_in[0];
    int best = -1;
    for (int i = 0; i < n_in; ++i) {
        if (in_sizes[i] > best) { best = in_sizes[i]; pos = (const float*)d_in[i]; }
    }

    float* outf = (float*)d_out;
    float* rowf = nullptr;
    float* colf = nullptr;
    if (out_size >= MTOT + 2 * MTOT * KNN) {
        rowf = outf + MTOT;
        colf = outf + MTOT + (size_t)MTOT * KNN;
    }

    fps_kernel<<<BB, FPS_T>>>(pos, outf);

    knn_kernel<<<(BB * M1) / WPB, KNN_T>>>(pos, rowf, colf);

    if (rowf != nullptr)
        dup_kernel<<<(OVSZ * KNN + 255) / 256, 256>>>(rowf, colf);
}